// round 3
// baseline (speedup 1.0000x reference)
#include <cuda_runtime.h>
#include <stdint.h>

#define N1 12800          // 100*128 elements of tm1
#define N2 25600          // 100*256 elements of tm2
#define NT 38400
#define K1 6399           // (N1-1)//2 -> torch lower-median rank
#define K2 12799
#define NBLOCKS 38        // 38*1024 = 38912 >= NT
#define CAP 2048          // compaction capacity for pass-2 survivors

// -------- device scratch (reset by finalize at end of every run) ----------
__device__ unsigned int g_keys[NT];          // mono-mapped keys
__device__ float        g_w[NT];             // 1 - 2*amask
__device__ unsigned int g_hist_cnt[2][2048]; // pass-1 count hists (zeroed at end)
__device__ float        g_hist_w[2][2048];   // pass-1 weight hists (zeroed at end)
__device__ double       g_sum_p1, g_sum_p2;  // sum (t - vmask)^2
__device__ double       g_sum_a1, g_sum_a2;  // sum amask^2
__device__ unsigned int g_arrive;            // last-block arrival counter

// order-preserving float -> uint
__device__ __forceinline__ unsigned int mono(unsigned int u) {
    return u ^ ((unsigned int)((int)u >> 31) | 0x80000000u);
}

// ---------------------------------------------------------------------------
// Block-wide: find bin containing rank *k_sh in hist[0..nb); updates *k_sh to
// rank-within-bin, returns selected bin. blockDim.x == 1024, nb in {1024,2048}.
// ---------------------------------------------------------------------------
__device__ unsigned int block_select(const unsigned int* hist, int nb,
                                     unsigned int* warpbuf,
                                     unsigned int* k_sh, unsigned int* sel_sh)
{
    int tid  = threadIdx.x;
    int lane = tid & 31;
    int warp = tid >> 5;
    int bpt  = nb >> 10;
    int base = tid * bpt;

    unsigned int local = 0;
    for (int j = 0; j < bpt; j++) local += hist[base + j];

    unsigned int incl = local;
    #pragma unroll
    for (int o = 1; o < 32; o <<= 1) {
        unsigned int t = __shfl_up_sync(0xffffffffu, incl, o);
        if (lane >= o) incl += t;
    }
    if (lane == 31) warpbuf[warp] = incl;
    __syncthreads();
    if (warp == 0) {
        unsigned int w = warpbuf[lane];
        unsigned int wi = w;
        #pragma unroll
        for (int o = 1; o < 32; o <<= 1) {
            unsigned int t = __shfl_up_sync(0xffffffffu, wi, o);
            if (lane >= o) wi += t;
        }
        warpbuf[lane] = wi - w;
    }
    __syncthreads();

    unsigned int ex = (incl - local) + warpbuf[warp];
    unsigned int k = *k_sh;
    __syncthreads();

    unsigned int c = ex;
    for (int j = 0; j < bpt; j++) {
        unsigned int h = hist[base + j];
        if (k >= c && k < c + h) {
            *sel_sh = (unsigned int)(base + j);
            *k_sh   = k - c;
        }
        c += h;
    }
    __syncthreads();
    return *sel_sh;
}

// block-wide float sum; all threads get the result
__device__ float block_sum(float v, float* redf)
{
    int lane = threadIdx.x & 31;
    int warp = threadIdx.x >> 5;
    #pragma unroll
    for (int o = 16; o; o >>= 1) v += __shfl_down_sync(0xffffffffu, v, o);
    if (lane == 0) redf[warp] = v;
    __syncthreads();
    if (warp == 0) {
        float r = redf[lane];
        #pragma unroll
        for (int o = 16; o; o >>= 1) r += __shfl_down_sync(0xffffffffu, r, o);
        if (lane == 0) redf[0] = r;
    }
    __syncthreads();
    float r = redf[0];
    __syncthreads();     // safe reuse of redf by caller
    return r;
}

// ---------------------------------------------------------------------------
// The single fused kernel.
// ---------------------------------------------------------------------------
__global__ void __launch_bounds__(1024) fused_kernel(
    const float* __restrict__ c2,  const float* __restrict__ c3,
    const float* __restrict__ vm1, const float* __restrict__ vm2,
    const float* __restrict__ am1, const float* __restrict__ am2,
    float* __restrict__ out)
{
    __shared__ unsigned int sh_cnt[2048];
    __shared__ float        sh_w[2048];
    __shared__ unsigned int sh_cnt3[1024];
    __shared__ float        sh_w3[1024];
    __shared__ unsigned int ck[CAP];
    __shared__ float        cw[CAP];
    __shared__ unsigned int warpbuf[32];
    __shared__ float        redf[32];
    __shared__ unsigned int k_sh, sel_sh, cnt_c;
    __shared__ bool         is_last;

    int tid  = threadIdx.x;
    int lane = tid & 31;
    int i    = blockIdx.x * 1024 + tid;

    // ===================== gather phase (all blocks) ========================
    float p1 = 0.f, p2 = 0.f, a1s = 0.f, a2s = 0.f;
    if (i < NT) {
        float t, v, a;
        int arr;
        int idx;
        if (i < N1) {
            t = c2[(size_t)i * 3136 + 399];   // [.,.,7,7]: 7*56+7
            v = vm1[i]; a = am1[i]; arr = 0;
        } else {
            idx = i - N1;
            t = c3[(size_t)idx * 784 + 87];   // [.,.,3,3]: 3*28+3
            v = vm2[idx]; a = am2[idx]; arr = 1;
        }
        unsigned int key = mono(__float_as_uint(t));
        g_keys[i] = key;
        float w = 1.0f - 2.0f * a;
        g_w[i] = w;
        atomicAdd(&g_hist_cnt[arr][key >> 21], 1u);
        atomicAdd(&g_hist_w[arr][key >> 21], w);
        float d = t - v;
        if (arr == 0) { p1 = d * d; a1s = a * a; }
        else          { p2 = d * d; a2s = a * a; }
    }
    // warp-reduce the 4 accumulators, lane0 atomic to global doubles
    #pragma unroll
    for (int o = 16; o; o >>= 1) {
        p1  += __shfl_down_sync(0xffffffffu, p1,  o);
        p2  += __shfl_down_sync(0xffffffffu, p2,  o);
        a1s += __shfl_down_sync(0xffffffffu, a1s, o);
        a2s += __shfl_down_sync(0xffffffffu, a2s, o);
    }
    if (lane == 0) {
        if (p1  != 0.f) atomicAdd(&g_sum_p1, (double)p1);
        if (p2  != 0.f) atomicAdd(&g_sum_p2, (double)p2);
        if (a1s != 0.f) atomicAdd(&g_sum_a1, (double)a1s);
        if (a2s != 0.f) atomicAdd(&g_sum_a2, (double)a2s);
    }

    // ===================== grid arrival =====================================
    __threadfence();          // release this block's writes device-wide
    __syncthreads();
    if (tid == 0) {
        unsigned int r = atomicAdd(&g_arrive, 1u);
        is_last = (r == (unsigned int)(gridDim.x - 1));
    }
    __syncthreads();
    if (!is_last) return;

    // ===================== finalize (last block only) =======================
    // read p components (all gather atomics are now globally visible)
    double sp1 = __ldcg(&g_sum_p1);
    double sp2 = __ldcg(&g_sum_p2);
    double sa1 = __ldcg(&g_sum_a1);
    double sa2 = __ldcg(&g_sum_a2);

    float S[2];
    const int   bases[2] = {0, N1};
    const int   ns[2]    = {N1, N2};
    const unsigned int ks[2] = {K1, K2};

    for (int arr = 0; arr < 2; arr++) {
        int base = bases[arr];
        int n    = ns[arr];

        // ---- level 1: load global 2048-bin cnt hist, select bin
        for (int b = tid; b < 2048; b += 1024)
            sh_cnt[b] = __ldcg(&g_hist_cnt[arr][b]);
        if (tid == 0) k_sh = ks[arr];
        __syncthreads();
        unsigned int d0 = block_select(sh_cnt, 2048, warpbuf, &k_sh, &sel_sh);

        float s1 = 0.f;
        for (int b = tid; b < 2048; b += 1024)
            if (b > (int)d0) s1 += __ldcg(&g_hist_w[arr][b]);
        float Sx = block_sum(s1, redf);

        // ---- level 2: scan keys, histogram bits[20:10] of matched, compact
        for (int b = tid; b < 2048; b += 1024) { sh_cnt[b] = 0u; sh_w[b] = 0.f; }
        if (tid == 0) cnt_c = 0u;
        __syncthreads();
        for (int j = base + tid; j < base + n; j += 1024) {
            unsigned int key = __ldcg(&g_keys[j]);
            if ((key >> 21) == d0) {
                float w = __ldcg(&g_w[j]);
                unsigned int b = (key >> 10) & 2047u;
                atomicAdd(&sh_cnt[b], 1u);
                atomicAdd(&sh_w[b], w);
                unsigned int pos = atomicAdd(&cnt_c, 1u);
                if (pos < CAP) { ck[pos] = key; cw[pos] = w; }
            }
        }
        __syncthreads();
        unsigned int d1 = block_select(sh_cnt, 2048, warpbuf, &k_sh, &sel_sh);

        float s2 = 0.f;
        for (int b = tid; b < 2048; b += 1024)
            if (b > (int)d1) s2 += sh_w[b];
        Sx += block_sum(s2, redf);

        // ---- level 3: bits[9:0] among elements matching (d0,d1)
        { int b = tid; sh_cnt3[b] = 0u; sh_w3[b] = 0.f; }
        __syncthreads();
        unsigned int nc = cnt_c;
        if (nc <= CAP) {
            for (unsigned int j = tid; j < nc; j += 1024) {
                unsigned int key = ck[j];
                if (((key >> 10) & 2047u) == d1) {
                    atomicAdd(&sh_cnt3[key & 1023u], 1u);
                    atomicAdd(&sh_w3[key & 1023u], cw[j]);
                }
            }
        } else {
            unsigned int p21 = (d0 << 11) | d1;
            for (int j = base + tid; j < base + n; j += 1024) {
                unsigned int key = __ldcg(&g_keys[j]);
                if ((key >> 10) == p21) {
                    atomicAdd(&sh_cnt3[key & 1023u], 1u);
                    atomicAdd(&sh_w3[key & 1023u], __ldcg(&g_w[j]));
                }
            }
        }
        __syncthreads();
        unsigned int d2 = block_select(sh_cnt3, 1024, warpbuf, &k_sh, &sel_sh);

        // suffix includes the median bin itself (t == m  ->  b = 1)
        float s3 = 0.f;
        { int b = tid; if (b >= (int)d2) s3 = sh_w3[b]; }
        Sx += block_sum(s3, redf);

        S[arr] = Sx;
    }

    // ===================== output + state reset =============================
    __syncthreads();
    for (int b = tid; b < 2048; b += 1024) {
        g_hist_cnt[0][b] = 0u;  g_hist_cnt[1][b] = 0u;
        g_hist_w[0][b]   = 0.f; g_hist_w[1][b]   = 0.f;
    }
    if (tid == 0) {
        double p = (sqrt(sp1) + sqrt(sp2)) * (1.0 / 38400.0);
        double q1sq = sa1 + (double)S[0];
        double q2sq = sa2 + (double)S[1];
        double q = (sqrt(q1sq) + sqrt(q2sq)) * (1.0 / 384.0);
        out[0] = (float)p;
        out[1] = (float)q;
        g_sum_p1 = 0.0; g_sum_p2 = 0.0;
        g_sum_a1 = 0.0; g_sum_a2 = 0.0;
        g_arrive = 0u;
    }
}

// ---------------------------------------------------------------------------
extern "C" void kernel_launch(void* const* d_in, const int* in_sizes, int n_in,
                              void* d_out, int out_size)
{
    const float* c2  = (const float*)d_in[0];
    const float* c3  = (const float*)d_in[1];
    const float* vm1 = (const float*)d_in[2];
    const float* vm2 = (const float*)d_in[3];
    const float* am1 = (const float*)d_in[4];
    const float* am2 = (const float*)d_in[5];
    float* out = (float*)d_out;

    fused_kernel<<<NBLOCKS, 1024>>>(c2, c3, vm1, vm2, am1, am2, out);
}

// round 4
// speedup vs baseline: 1.5023x; 1.5023x over previous
#include <cuda_runtime.h>
#include <stdint.h>

#define N1 12800          // 100*128 elements of tm1
#define N2 25600          // 100*256 elements of tm2
#define NT 38400
#define K1 6399           // (N1-1)//2 -> torch lower-median rank
#define K2 12799
#define NBLOCKS 148       // one block per SM
#define EPB 260           // elements per block: 148*260 = 38480 >= 38400
#define CAP 2048          // per-bin bucket capacity (uint16 indices)

// -------- device scratch (reset by finalize at end of every run) ----------
__device__ unsigned int   g_keys[NT];           // mono keys (per array, concatenated)
__device__ float          g_w[NT];              // 1 - 2*amask
__device__ unsigned int   g_bcnt[2][2048];      // per-bin counts (== level-1 hist)
__device__ float          g_hist_w[2][2048];    // per-bin weight sums
__device__ unsigned short g_bidx[2 * 2048 * CAP]; // per-bin element indices (16 MB)
__device__ double         g_sum_p1, g_sum_p2;   // sum (t - vmask)^2
__device__ double         g_sum_a1, g_sum_a2;   // sum amask^2
__device__ unsigned int   g_arrive;

__device__ __forceinline__ unsigned int mono(unsigned int u) {
    return u ^ ((unsigned int)((int)u >> 31) | 0x80000000u);
}

// ---------------------------------------------------------------------------
// Block-wide: find bin containing rank *k_sh in hist[0..nb); update *k_sh to
// rank-within-bin; return bin. blockDim.x == 1024, nb in {1024, 2048}.
// ---------------------------------------------------------------------------
__device__ unsigned int block_select(const unsigned int* hist, int nb,
                                     unsigned int* warpbuf,
                                     unsigned int* k_sh, unsigned int* sel_sh)
{
    int tid  = threadIdx.x;
    int lane = tid & 31;
    int warp = tid >> 5;
    int bpt  = nb >> 10;
    int base = tid * bpt;

    unsigned int local = 0;
    for (int j = 0; j < bpt; j++) local += hist[base + j];

    unsigned int incl = local;
    #pragma unroll
    for (int o = 1; o < 32; o <<= 1) {
        unsigned int t = __shfl_up_sync(0xffffffffu, incl, o);
        if (lane >= o) incl += t;
    }
    if (lane == 31) warpbuf[warp] = incl;
    __syncthreads();
    if (warp == 0) {
        unsigned int w = warpbuf[lane];
        unsigned int wi = w;
        #pragma unroll
        for (int o = 1; o < 32; o <<= 1) {
            unsigned int t = __shfl_up_sync(0xffffffffu, wi, o);
            if (lane >= o) wi += t;
        }
        warpbuf[lane] = wi - w;
    }
    __syncthreads();

    unsigned int ex = (incl - local) + warpbuf[warp];
    unsigned int k = *k_sh;
    __syncthreads();

    unsigned int c = ex;
    for (int j = 0; j < bpt; j++) {
        unsigned int h = hist[base + j];
        if (k >= c && k < c + h) {
            *sel_sh = (unsigned int)(base + j);
            *k_sh   = k - c;
        }
        c += h;
    }
    __syncthreads();
    return *sel_sh;
}

// block-wide float sum; all threads receive the result
__device__ float block_sum(float v, float* redf)
{
    int lane = threadIdx.x & 31;
    int warp = threadIdx.x >> 5;
    #pragma unroll
    for (int o = 16; o; o >>= 1) v += __shfl_down_sync(0xffffffffu, v, o);
    if (lane == 0) redf[warp] = v;
    __syncthreads();
    if (warp == 0) {
        float r = redf[lane];
        #pragma unroll
        for (int o = 16; o; o >>= 1) r += __shfl_down_sync(0xffffffffu, r, o);
        if (lane == 0) redf[0] = r;
    }
    __syncthreads();
    float r = redf[0];
    __syncthreads();
    return r;
}

// ---------------------------------------------------------------------------
__global__ void __launch_bounds__(1024) fused_kernel(
    const float* __restrict__ c2,  const float* __restrict__ c3,
    const float* __restrict__ vm1, const float* __restrict__ vm2,
    const float* __restrict__ am1, const float* __restrict__ am2,
    float* __restrict__ out)
{
    __shared__ unsigned int sh_cnt[2048];
    __shared__ unsigned int warpbuf[32];
    __shared__ float        redf[32];
    __shared__ unsigned int k_sh, sel_sh;
    __shared__ bool         is_last;

    int tid  = threadIdx.x;
    int lane = tid & 31;

    // ===================== gather (all blocks, 260 elems each) ==============
    float p1 = 0.f, p2 = 0.f, a1s = 0.f, a2s = 0.f;
    int e = blockIdx.x * EPB + tid;
    if (tid < EPB && e < NT) {
        float t, v, a;
        int arr, idx;
        if (e < N1) {
            t = c2[(size_t)e * 3136 + 399];   // [.,.,7,7]: 7*56+7
            v = vm1[e]; a = am1[e]; arr = 0; idx = e;
        } else {
            idx = e - N1;
            t = c3[(size_t)idx * 784 + 87];   // [.,.,3,3]: 3*28+3
            v = vm2[idx]; a = am2[idx]; arr = 1;
        }
        unsigned int key = mono(__float_as_uint(t));
        float w = 1.0f - 2.0f * a;
        g_keys[e] = key;
        g_w[e]    = w;
        unsigned int bin = key >> 21;
        unsigned int pos = atomicAdd(&g_bcnt[arr][bin], 1u);
        if (pos < CAP)
            g_bidx[(((unsigned)arr << 11) | bin) * CAP + pos] = (unsigned short)idx;
        atomicAdd(&g_hist_w[arr][bin], w);
        float d = t - v;
        if (arr == 0) { p1 = d * d; a1s = a * a; }
        else          { p2 = d * d; a2s = a * a; }
    }
    #pragma unroll
    for (int o = 16; o; o >>= 1) {
        p1  += __shfl_down_sync(0xffffffffu, p1,  o);
        p2  += __shfl_down_sync(0xffffffffu, p2,  o);
        a1s += __shfl_down_sync(0xffffffffu, a1s, o);
        a2s += __shfl_down_sync(0xffffffffu, a2s, o);
    }
    if (lane == 0) {
        if (p1  != 0.f) atomicAdd(&g_sum_p1, (double)p1);
        if (p2  != 0.f) atomicAdd(&g_sum_p2, (double)p2);
        if (a1s != 0.f) atomicAdd(&g_sum_a1, (double)a1s);
        if (a2s != 0.f) atomicAdd(&g_sum_a2, (double)a2s);
    }

    // ===================== grid arrival =====================================
    __threadfence();
    __syncthreads();
    if (tid == 0) {
        unsigned int r = atomicAdd(&g_arrive, 1u);
        is_last = (r == (unsigned int)(gridDim.x - 1));
    }
    __syncthreads();
    if (!is_last) return;

    // ===================== finalize (last block only) =======================
    double sp1 = __ldcg(&g_sum_p1);
    double sp2 = __ldcg(&g_sum_p2);
    double sa1 = __ldcg(&g_sum_a1);
    double sa2 = __ldcg(&g_sum_a2);

    float S[2];
    const int   bases[2] = {0, N1};
    const int   ns[2]    = {N1, N2};
    const unsigned int kranks[2] = {K1, K2};

    for (int arr = 0; arr < 2; arr++) {
        int base = bases[arr];
        int n    = ns[arr];

        // ---- level 1: bin counters are the histogram
        for (int b = tid; b < 2048; b += 1024)
            sh_cnt[b] = __ldcg(&g_bcnt[arr][b]);
        if (tid == 0) k_sh = kranks[arr];
        __syncthreads();
        unsigned int d0 = block_select(sh_cnt, 2048, warpbuf, &k_sh, &sel_sh);

        // suffix weight over bins strictly above d0
        float s1 = 0.f;
        for (int b = tid; b < 2048; b += 1024)
            if (b > (int)d0) s1 += __ldcg(&g_hist_w[arr][b]);
        float Sx = block_sum(s1, redf);

        unsigned int nc = sh_cnt[d0];
        __syncthreads();

        unsigned int mkey;
        if (nc <= CAP) {
            // ---- load bin elements (<= 2 per thread)
            const unsigned short* bp = &g_bidx[(((unsigned)arr << 11) | d0) * CAP];
            unsigned int key0 = 0u, key1 = 0u;
            float        w0 = 0.f, w1 = 0.f;
            bool h0 = (tid < (int)nc), h1 = (tid + 1024 < (int)nc);
            if (h0) {
                int ix = __ldcg(&bp[tid]);
                key0 = __ldcg(&g_keys[base + ix]);
                w0   = __ldcg(&g_w[base + ix]);
            }
            if (h1) {
                int ix = __ldcg(&bp[tid + 1024]);
                key1 = __ldcg(&g_keys[base + ix]);
                w1   = __ldcg(&g_w[base + ix]);
            }
            // ---- level 2: bits [20:10]
            for (int b = tid; b < 2048; b += 1024) sh_cnt[b] = 0u;
            __syncthreads();
            if (h0) atomicAdd(&sh_cnt[(key0 >> 10) & 2047u], 1u);
            if (h1) atomicAdd(&sh_cnt[(key1 >> 10) & 2047u], 1u);
            __syncthreads();
            unsigned int d1 = block_select(sh_cnt, 2048, warpbuf, &k_sh, &sel_sh);
            // ---- level 3: bits [9:0]
            sh_cnt[tid] = 0u;
            __syncthreads();
            if (h0 && ((key0 >> 10) & 2047u) == d1) atomicAdd(&sh_cnt[key0 & 1023u], 1u);
            if (h1 && ((key1 >> 10) & 2047u) == d1) atomicAdd(&sh_cnt[key1 & 1023u], 1u);
            __syncthreads();
            unsigned int d2 = block_select(sh_cnt, 1024, warpbuf, &k_sh, &sel_sh);
            mkey = (d0 << 21) | (d1 << 10) | d2;
            // ---- within-bin suffix (>= median key, ties included)
            float s = 0.f;
            if (h0 && key0 >= mkey) s += w0;
            if (h1 && key1 >= mkey) s += w1;
            Sx += block_sum(s, redf);
        } else {
            // ---- fallback: full rescan (bin overflowed CAP)
            for (int b = tid; b < 2048; b += 1024) sh_cnt[b] = 0u;
            __syncthreads();
            for (int j = base + tid; j < base + n; j += 1024) {
                unsigned int key = __ldcg(&g_keys[j]);
                if ((key >> 21) == d0) atomicAdd(&sh_cnt[(key >> 10) & 2047u], 1u);
            }
            __syncthreads();
            unsigned int d1 = block_select(sh_cnt, 2048, warpbuf, &k_sh, &sel_sh);
            unsigned int p21 = (d0 << 11) | d1;
            sh_cnt[tid] = 0u;
            __syncthreads();
            for (int j = base + tid; j < base + n; j += 1024) {
                unsigned int key = __ldcg(&g_keys[j]);
                if ((key >> 10) == p21) atomicAdd(&sh_cnt[key & 1023u], 1u);
            }
            __syncthreads();
            unsigned int d2 = block_select(sh_cnt, 1024, warpbuf, &k_sh, &sel_sh);
            mkey = (p21 << 10) | d2;
            float s = 0.f;
            for (int j = base + tid; j < base + n; j += 1024) {
                unsigned int key = __ldcg(&g_keys[j]);
                if ((key >> 21) == d0 && key >= mkey) s += __ldcg(&g_w[j]);
            }
            Sx += block_sum(s, redf);
        }
        S[arr] = Sx;
    }

    // ===================== output + state reset =============================
    __syncthreads();
    for (int b = tid; b < 2048; b += 1024) {
        g_bcnt[0][b] = 0u;  g_bcnt[1][b] = 0u;
        g_hist_w[0][b] = 0.f; g_hist_w[1][b] = 0.f;
    }
    if (tid == 0) {
        double p = (sqrt(sp1) + sqrt(sp2)) * (1.0 / 38400.0);
        double q1sq = sa1 + (double)S[0];
        double q2sq = sa2 + (double)S[1];
        double q = (sqrt(q1sq) + sqrt(q2sq)) * (1.0 / 384.0);
        out[0] = (float)p;
        out[1] = (float)q;
        g_sum_p1 = 0.0; g_sum_p2 = 0.0;
        g_sum_a1 = 0.0; g_sum_a2 = 0.0;
        g_arrive = 0u;
    }
}

// ---------------------------------------------------------------------------
extern "C" void kernel_launch(void* const* d_in, const int* in_sizes, int n_in,
                              void* d_out, int out_size)
{
    const float* c2  = (const float*)d_in[0];
    const float* c3  = (const float*)d_in[1];
    const float* vm1 = (const float*)d_in[2];
    const float* vm2 = (const float*)d_in[3];
    const float* am1 = (const float*)d_in[4];
    const float* am2 = (const float*)d_in[5];
    float* out = (float*)d_out;

    fused_kernel<<<NBLOCKS, 1024>>>(c2, c3, vm1, vm2, am1, am2, out);
}

// round 5
// speedup vs baseline: 1.6318x; 1.0862x over previous
#include <cuda_runtime.h>
#include <stdint.h>

#define N1 12800          // 100*128 elements of tm1
#define N2 25600          // 100*256 elements of tm2
#define NT 38400
#define K1 6399           // (N1-1)//2 -> torch lower-median rank
#define K2 12799
#define NBLOCKS 148
#define EPB 260           // 148*260 = 38480 >= 38400
#define CAP 2048          // per-bin bucket capacity
#define SMALL 512         // small-set selection threshold

// -------- device scratch (reset by finalize at end of every run) ----------
__device__ unsigned int g_keys[NT];             // full key array (fallback only)
__device__ float        g_w[NT];                // full weight array (fallback only)
__device__ unsigned int g_bcnt[2][2048];        // per-bin counts (= level-1 hist)
__device__ float        g_hist_w[2][2048];      // per-bin weight sums
__device__ unsigned int g_bkey[2 * 2048 * CAP]; // bucketed keys   (32 MB)
__device__ float        g_bw[2 * 2048 * CAP];   // bucketed weights(32 MB)
__device__ double       g_sum_p1, g_sum_p2;     // sum (t - vmask)^2
__device__ double       g_sum_a1, g_sum_a2;     // sum amask^2
__device__ unsigned int g_arrive;

__device__ __forceinline__ unsigned int mono(unsigned int u) {
    return u ^ ((unsigned int)((int)u >> 31) | 0x80000000u);
}

// ---------------------------------------------------------------------------
// Block-wide: find bin containing rank *k_sh in hist[0..nb); update *k_sh to
// rank-within-bin; return bin. blockDim.x == 1024, nb in {1024, 2048}.
// ---------------------------------------------------------------------------
__device__ unsigned int block_select(const unsigned int* hist, int nb,
                                     unsigned int* warpbuf,
                                     unsigned int* k_sh, unsigned int* sel_sh)
{
    int tid  = threadIdx.x;
    int lane = tid & 31;
    int warp = tid >> 5;
    int bpt  = nb >> 10;
    int base = tid * bpt;

    unsigned int local = 0;
    for (int j = 0; j < bpt; j++) local += hist[base + j];

    unsigned int incl = local;
    #pragma unroll
    for (int o = 1; o < 32; o <<= 1) {
        unsigned int t = __shfl_up_sync(0xffffffffu, incl, o);
        if (lane >= o) incl += t;
    }
    if (lane == 31) warpbuf[warp] = incl;
    __syncthreads();
    if (warp == 0) {
        unsigned int w = warpbuf[lane];
        unsigned int wi = w;
        #pragma unroll
        for (int o = 1; o < 32; o <<= 1) {
            unsigned int t = __shfl_up_sync(0xffffffffu, wi, o);
            if (lane >= o) wi += t;
        }
        warpbuf[lane] = wi - w;
    }
    __syncthreads();

    unsigned int ex = (incl - local) + warpbuf[warp];
    unsigned int k = *k_sh;
    __syncthreads();

    unsigned int c = ex;
    for (int j = 0; j < bpt; j++) {
        unsigned int h = hist[base + j];
        if (k >= c && k < c + h) {
            *sel_sh = (unsigned int)(base + j);
            *k_sh   = k - c;
        }
        c += h;
    }
    __syncthreads();
    return *sel_sh;
}

// block-wide float sum; all threads receive the result
__device__ float block_sum(float v, float* redf)
{
    int lane = threadIdx.x & 31;
    int warp = threadIdx.x >> 5;
    #pragma unroll
    for (int o = 16; o; o >>= 1) v += __shfl_down_sync(0xffffffffu, v, o);
    if (lane == 0) redf[warp] = v;
    __syncthreads();
    if (warp == 0) {
        float r = redf[lane];
        #pragma unroll
        for (int o = 16; o; o >>= 1) r += __shfl_down_sync(0xffffffffu, r, o);
        if (lane == 0) redf[0] = r;
    }
    __syncthreads();
    float r = redf[0];
    __syncthreads();
    return r;
}

// ---------------------------------------------------------------------------
__global__ void __launch_bounds__(1024) fused_kernel(
    const float* __restrict__ c2,  const float* __restrict__ c3,
    const float* __restrict__ vm1, const float* __restrict__ vm2,
    const float* __restrict__ am1, const float* __restrict__ am2,
    float* __restrict__ out)
{
    __shared__ unsigned int sh_cnt[2048];
    __shared__ float        sh_w[2048];
    __shared__ unsigned int sk[SMALL];
    __shared__ float        sw[SMALL];
    __shared__ unsigned int warpbuf[32];
    __shared__ float        redf[32];
    __shared__ unsigned int k_sh, sel_sh, mkey_sh;
    __shared__ bool         is_last;

    int tid  = threadIdx.x;
    int lane = tid & 31;

    // ===================== gather (all blocks, EPB elems each) ==============
    float p1 = 0.f, p2 = 0.f, a1s = 0.f, a2s = 0.f;
    int e = blockIdx.x * EPB + tid;
    if (tid < EPB && e < NT) {
        float t, v, a;
        int arr;
        if (e < N1) {
            t = c2[(size_t)e * 3136 + 399];         // [.,.,7,7]: 7*56+7
            v = vm1[e]; a = am1[e]; arr = 0;
        } else {
            int idx = e - N1;
            t = c3[(size_t)idx * 784 + 87];         // [.,.,3,3]: 3*28+3
            v = vm2[idx]; a = am2[idx]; arr = 1;
        }
        unsigned int key = mono(__float_as_uint(t));
        float w = 1.0f - 2.0f * a;
        g_keys[e] = key;                            // fallback-path data
        g_w[e]    = w;
        unsigned int bin = key >> 21;
        unsigned int pos = atomicAdd(&g_bcnt[arr][bin], 1u);
        if (pos < CAP) {
            size_t slot = (size_t)(((unsigned)arr << 11) | bin) * CAP + pos;
            g_bkey[slot] = key;
            g_bw[slot]   = w;
        }
        atomicAdd(&g_hist_w[arr][bin], w);
        float d = t - v;
        if (arr == 0) { p1 = d * d; a1s = a * a; }
        else          { p2 = d * d; a2s = a * a; }
    }
    #pragma unroll
    for (int o = 16; o; o >>= 1) {
        p1  += __shfl_down_sync(0xffffffffu, p1,  o);
        p2  += __shfl_down_sync(0xffffffffu, p2,  o);
        a1s += __shfl_down_sync(0xffffffffu, a1s, o);
        a2s += __shfl_down_sync(0xffffffffu, a2s, o);
    }
    if (lane == 0) {
        if (p1  != 0.f) atomicAdd(&g_sum_p1, (double)p1);
        if (p2  != 0.f) atomicAdd(&g_sum_p2, (double)p2);
        if (a1s != 0.f) atomicAdd(&g_sum_a1, (double)a1s);
        if (a2s != 0.f) atomicAdd(&g_sum_a2, (double)a2s);
    }

    // ===================== grid arrival =====================================
    __threadfence();
    __syncthreads();
    if (tid == 0) {
        unsigned int r = atomicAdd(&g_arrive, 1u);
        is_last = (r == (unsigned int)(gridDim.x - 1));
    }
    __syncthreads();
    if (!is_last) return;

    // ===================== finalize (last block only) =======================
    double sp1 = __ldcg(&g_sum_p1);
    double sp2 = __ldcg(&g_sum_p2);
    double sa1 = __ldcg(&g_sum_a1);
    double sa2 = __ldcg(&g_sum_a2);

    float S[2];
    const int   bases[2] = {0, N1};
    const int   ns[2]    = {N1, N2};
    const unsigned int kranks[2] = {K1, K2};

    for (int arr = 0; arr < 2; arr++) {
        int base = bases[arr];
        int n    = ns[arr];

        // ---- batched prefetch of cnt + weight hists into shared (high MLP)
        for (int b = tid; b < 2048; b += 1024) {
            sh_cnt[b] = __ldcg(&g_bcnt[arr][b]);
            sh_w[b]   = __ldcg(&g_hist_w[arr][b]);
        }
        if (tid == 0) k_sh = kranks[arr];
        __syncthreads();

        // ---- level 1: select bin holding the median rank
        unsigned int d0 = block_select(sh_cnt, 2048, warpbuf, &k_sh, &sel_sh);

        // suffix weight over bins strictly above d0
        float s1 = 0.f;
        for (int b = tid; b < 2048; b += 1024)
            if (b > (int)d0) s1 += sh_w[b];
        float Sx = block_sum(s1, redf);

        unsigned int nc = sh_cnt[d0];
        unsigned int k  = k_sh;                 // rank within bin
        __syncthreads();
        size_t slotbase = (size_t)(((unsigned)arr << 11) | d0) * CAP;

        if (nc <= SMALL) {
            // ======= small-set path (expected: nc ~ 10..50 for randn) =======
            if (tid < (int)nc) {
                sk[tid] = __ldcg(&g_bkey[slotbase + tid]);
                sw[tid] = __ldcg(&g_bw[slotbase + tid]);
            }
            __syncthreads();
            if (tid < (int)nc) {
                unsigned int key = sk[tid];
                unsigned int less = 0, eq = 0;
                for (unsigned int j = 0; j < nc; j++) {
                    unsigned int kj = sk[j];
                    less += (kj < key);
                    eq   += (kj == key);
                }
                if (less <= k && k < less + eq) mkey_sh = key;
            }
            __syncthreads();
            unsigned int mkey = mkey_sh;
            float s = (tid < (int)nc && sk[tid] >= mkey) ? sw[tid] : 0.f;
            Sx += block_sum(s, redf);
        } else if (nc <= CAP) {
            // ======= histogram path over the bucket =======
            unsigned int key0 = 0u, key1 = 0u;
            float        w0 = 0.f, w1 = 0.f;
            bool h0 = (tid < (int)nc), h1 = (tid + 1024 < (int)nc);
            if (h0) { key0 = __ldcg(&g_bkey[slotbase + tid]);
                      w0   = __ldcg(&g_bw[slotbase + tid]); }
            if (h1) { key1 = __ldcg(&g_bkey[slotbase + tid + 1024]);
                      w1   = __ldcg(&g_bw[slotbase + tid + 1024]); }
            // level 2: bits [20:10]
            for (int b = tid; b < 2048; b += 1024) sh_cnt[b] = 0u;
            __syncthreads();
            if (h0) atomicAdd(&sh_cnt[(key0 >> 10) & 2047u], 1u);
            if (h1) atomicAdd(&sh_cnt[(key1 >> 10) & 2047u], 1u);
            __syncthreads();
            unsigned int d1 = block_select(sh_cnt, 2048, warpbuf, &k_sh, &sel_sh);
            // level 3: bits [9:0]
            sh_cnt[tid] = 0u;
            __syncthreads();
            if (h0 && ((key0 >> 10) & 2047u) == d1) atomicAdd(&sh_cnt[key0 & 1023u], 1u);
            if (h1 && ((key1 >> 10) & 2047u) == d1) atomicAdd(&sh_cnt[key1 & 1023u], 1u);
            __syncthreads();
            unsigned int d2 = block_select(sh_cnt, 1024, warpbuf, &k_sh, &sel_sh);
            unsigned int mkey = (d0 << 21) | (d1 << 10) | d2;
            float s = 0.f;
            if (h0 && key0 >= mkey) s += w0;
            if (h1 && key1 >= mkey) s += w1;
            Sx += block_sum(s, redf);
        } else {
            // ======= fallback: bucket overflowed, rescan full key array =====
            for (int b = tid; b < 2048; b += 1024) sh_cnt[b] = 0u;
            __syncthreads();
            for (int j = base + tid; j < base + n; j += 1024) {
                unsigned int key = __ldcg(&g_keys[j]);
                if ((key >> 21) == d0) atomicAdd(&sh_cnt[(key >> 10) & 2047u], 1u);
            }
            __syncthreads();
            unsigned int d1 = block_select(sh_cnt, 2048, warpbuf, &k_sh, &sel_sh);
            unsigned int p21 = (d0 << 11) | d1;
            sh_cnt[tid] = 0u;
            __syncthreads();
            for (int j = base + tid; j < base + n; j += 1024) {
                unsigned int key = __ldcg(&g_keys[j]);
                if ((key >> 10) == p21) atomicAdd(&sh_cnt[key & 1023u], 1u);
            }
            __syncthreads();
            unsigned int d2 = block_select(sh_cnt, 1024, warpbuf, &k_sh, &sel_sh);
            unsigned int mkey = (p21 << 10) | d2;
            float s = 0.f;
            for (int j = base + tid; j < base + n; j += 1024) {
                unsigned int key = __ldcg(&g_keys[j]);
                if ((key >> 21) == d0 && key >= mkey) s += __ldcg(&g_w[j]);
            }
            Sx += block_sum(s, redf);
        }
        S[arr] = Sx;
    }

    // ===================== output + state reset =============================
    __syncthreads();
    for (int b = tid; b < 2048; b += 1024) {
        g_bcnt[0][b] = 0u;   g_bcnt[1][b] = 0u;
        g_hist_w[0][b] = 0.f; g_hist_w[1][b] = 0.f;
    }
    if (tid == 0) {
        double p = (sqrt(sp1) + sqrt(sp2)) * (1.0 / 38400.0);
        double q1sq = sa1 + (double)S[0];
        double q2sq = sa2 + (double)S[1];
        double q = (sqrt(q1sq) + sqrt(q2sq)) * (1.0 / 384.0);
        out[0] = (float)p;
        out[1] = (float)q;
        g_sum_p1 = 0.0; g_sum_p2 = 0.0;
        g_sum_a1 = 0.0; g_sum_a2 = 0.0;
        g_arrive = 0u;
    }
}

// ---------------------------------------------------------------------------
extern "C" void kernel_launch(void* const* d_in, const int* in_sizes, int n_in,
                              void* d_out, int out_size)
{
    const float* c2  = (const float*)d_in[0];
    const float* c3  = (const float*)d_in[1];
    const float* vm1 = (const float*)d_in[2];
    const float* vm2 = (const float*)d_in[3];
    const float* am1 = (const float*)d_in[4];
    const float* am2 = (const float*)d_in[5];
    float* out = (float*)d_out;

    fused_kernel<<<NBLOCKS, 1024>>>(c2, c3, vm1, vm2, am1, am2, out);
}